// round 13
// baseline (speedup 1.0000x reference)
#include <cuda_runtime.h>
#include <cuda_bf16.h>
#include <math.h>
#include <cstdint>

#define BATCH 2
#define SEQ   2048
#define DIM   1024
#define NH    16
#define HD    64
#define NTOK  4096

typedef __nv_bfloat16 bf16;

// ---------------------------------------------------------------------------
// Scratch (__device__ globals; no allocation)
// ---------------------------------------------------------------------------
__device__ bf16 g_qh[(size_t)NTOK * 3 * DIM];   // qkv hi  [4096,3072]
__device__ bf16 g_ql[(size_t)NTOK * 3 * DIM];   // qkv lo
__device__ bf16 g_ah[(size_t)NTOK * DIM];       // GEMM A hi / attn out hi
__device__ bf16 g_al[(size_t)NTOK * DIM];       // GEMM A lo / attn out lo
__device__ bf16 g_bh[(size_t)3 * DIM * DIM];    // W^T hi [N,K]
__device__ bf16 g_bl[(size_t)3 * DIM * DIM];    // W^T lo

// ---------------------------------------------------------------------------
// MMA / LDSM / cp.async primitives (arch-neutral on compute_103)
// ---------------------------------------------------------------------------
__device__ __forceinline__ void mma16816(float* c, const uint32_t* a, const uint32_t* b) {
    asm volatile(
        "mma.sync.aligned.m16n8k16.row.col.f32.bf16.bf16.f32 "
        "{%0,%1,%2,%3}, {%4,%5,%6,%7}, {%8,%9}, {%0,%1,%2,%3};"
        : "+f"(c[0]), "+f"(c[1]), "+f"(c[2]), "+f"(c[3])
        : "r"(a[0]), "r"(a[1]), "r"(a[2]), "r"(a[3]), "r"(b[0]), "r"(b[1]));
}
__device__ __forceinline__ uint32_t cvta_smem(const void* p) {
    uint32_t a;
    asm("{ .reg .u64 t; cvta.to.shared.u64 t, %1; cvt.u32.u64 %0, t; }" : "=r"(a) : "l"(p));
    return a;
}
__device__ __forceinline__ void ldsm_x4(uint32_t* r, uint32_t addr) {
    asm volatile("ldmatrix.sync.aligned.m8n8.x4.shared.b16 {%0,%1,%2,%3}, [%4];"
                 : "=r"(r[0]), "=r"(r[1]), "=r"(r[2]), "=r"(r[3]) : "r"(addr));
}
__device__ __forceinline__ void ldsm_x4_t(uint32_t* r, uint32_t addr) {
    asm volatile("ldmatrix.sync.aligned.m8n8.x4.trans.shared.b16 {%0,%1,%2,%3}, [%4];"
                 : "=r"(r[0]), "=r"(r[1]), "=r"(r[2]), "=r"(r[3]) : "r"(addr));
}
__device__ __forceinline__ void cp_async16(uint32_t dst, const void* src) {
    asm volatile("cp.async.cg.shared.global [%0], [%1], 16;" :: "r"(dst), "l"(src));
}
#define CP_COMMIT() asm volatile("cp.async.commit_group;" ::: "memory")
#define CP_WAIT1()  asm volatile("cp.async.wait_group 1;" ::: "memory")
#define CP_WAIT0()  asm volatile("cp.async.wait_group 0;" ::: "memory")

__device__ __forceinline__ void split2(float x, float y, uint32_t& hi, uint32_t& lo) {
    __nv_bfloat16 hx = __float2bfloat16(x);
    __nv_bfloat16 hy = __float2bfloat16(y);
    __nv_bfloat162 h2(hx, hy);
    __nv_bfloat162 l2(__float2bfloat16(x - __bfloat162float(hx)),
                      __float2bfloat16(y - __bfloat162float(hy)));
    hi = *(uint32_t*)&h2;
    lo = *(uint32_t*)&l2;
}

// ---------------------------------------------------------------------------
// fp32 -> bf16 hi/lo elementwise split
// ---------------------------------------------------------------------------
__global__ __launch_bounds__(256)
void split_kernel(const float* __restrict__ in, bf16* __restrict__ hi,
                  bf16* __restrict__ lo, int n4)
{
    int i = blockIdx.x * blockDim.x + threadIdx.x;
    if (i >= n4) return;
    float4 v = *(const float4*)&in[i * 4];
    uint32_t h01, l01, h23, l23;
    split2(v.x, v.y, h01, l01);
    split2(v.z, v.w, h23, l23);
    *(uint32_t*)&hi[i * 4]     = h01;
    *(uint32_t*)&hi[i * 4 + 2] = h23;
    *(uint32_t*)&lo[i * 4]     = l01;
    *(uint32_t*)&lo[i * 4 + 2] = l23;
}

// W[K,N] fp32 -> hi/lo [N,K] bf16 (transpose + split)
__global__ __launch_bounds__(256)
void splitT_kernel(const float* __restrict__ W, bf16* __restrict__ hi,
                   bf16* __restrict__ lo, int K, int N)
{
    __shared__ float t[32][33];
    const int n0 = blockIdx.x * 32, k0 = blockIdx.y * 32;
    const int tx = threadIdx.x, ty = threadIdx.y;
#pragma unroll
    for (int r = 0; r < 4; ++r)
        t[ty + r * 8][tx] = W[(size_t)(k0 + ty + r * 8) * N + n0 + tx];
    __syncthreads();
#pragma unroll
    for (int r = 0; r < 4; ++r) {
        int nl = ty + r * 8;
        float x = t[tx][nl];
        __nv_bfloat16 h = __float2bfloat16(x);
        __nv_bfloat16 l = __float2bfloat16(x - __bfloat162float(h));
        size_t o = (size_t)(n0 + nl) * K + k0 + tx;
        hi[o] = h; lo[o] = l;
    }
}

// ---------------------------------------------------------------------------
// HMMA split-bf16 GEMM (unchanged from R11)
// ---------------------------------------------------------------------------
#define GEMM_SMEM (4 * 128 * 144)   // 73728 B

__global__ __launch_bounds__(256)
void hmma_gemm(const bf16* __restrict__ Ah, const bf16* __restrict__ Al,
               const bf16* __restrict__ Bh, const bf16* __restrict__ Bl,
               const float* __restrict__ bias,
               float* __restrict__ Cf, bf16* __restrict__ Chi, bf16* __restrict__ Clo,
               int M, int N, int K)
{
    extern __shared__ char sm[];
    char* tAh = sm;
    char* tAl = sm + 128 * 144;
    char* tBh = sm + 2 * 128 * 144;
    char* tBl = sm + 3 * 128 * 144;

    const int tid = threadIdx.x;
    const int w   = tid >> 5, lane = tid & 31;
    const int g   = lane >> 2, tg = lane & 3;
    const int grp = lane >> 3, ri = lane & 7;
    const int wm  = w & 1;
    const int wn  = w >> 1;
    const int m0  = blockIdx.y * 128, n0 = blockIdx.x * 128;

    const uint32_t sAh = cvta_smem(tAh), sAl = cvta_smem(tAl);
    const uint32_t sBh = cvta_smem(tBh), sBl = cvta_smem(tBl);
    const uint32_t aLane = (uint32_t)(((grp & 1) * 8 + ri) * 144 + ((grp >> 1) & 1) * 16);
    const uint32_t bLane = (uint32_t)((((grp >> 1) & 1) * 8 + ri) * 144 + (grp & 1) * 16);

    float acc[4][4][4];
#pragma unroll
    for (int a = 0; a < 4; ++a)
#pragma unroll
        for (int b = 0; b < 4; ++b)
#pragma unroll
            for (int c = 0; c < 4; ++c) acc[a][b][c] = 0.0f;

    for (int ch = 0; ch < K / 64; ++ch) {
        const int k0 = ch * 64;
#pragma unroll 4
        for (int i = tid; i < 1024; i += 256) {
            int r = i >> 3, cc = i & 7;
            size_t aofs = (size_t)(m0 + r) * K + k0 + cc * 8;
            size_t bofs = (size_t)(n0 + r) * K + k0 + cc * 8;
            *(uint4*)(tAh + r * 144 + cc * 16) = *(const uint4*)(Ah + aofs);
            *(uint4*)(tAl + r * 144 + cc * 16) = *(const uint4*)(Al + aofs);
            *(uint4*)(tBh + r * 144 + cc * 16) = *(const uint4*)(Bh + bofs);
            *(uint4*)(tBl + r * 144 + cc * 16) = *(const uint4*)(Bl + bofs);
        }
        __syncthreads();

#pragma unroll
        for (int ks = 0; ks < 4; ++ks) {
            uint32_t fah[4][4], fal[4][4];
#pragma unroll
            for (int mt = 0; mt < 4; ++mt) {
                uint32_t ro = (uint32_t)((wm * 64 + mt * 16) * 144 + ks * 32) + aLane;
                ldsm_x4(fah[mt], sAh + ro);
                ldsm_x4(fal[mt], sAl + ro);
            }
            uint32_t fbh[2][4], fbl[2][4];
#pragma unroll
            for (int ntp = 0; ntp < 2; ++ntp) {
                uint32_t ro = (uint32_t)((wn * 32 + ntp * 16) * 144 + ks * 32) + bLane;
                ldsm_x4(fbh[ntp], sBh + ro);
                ldsm_x4(fbl[ntp], sBl + ro);
            }
#pragma unroll
            for (int mt = 0; mt < 4; ++mt)
#pragma unroll
                for (int nt = 0; nt < 4; ++nt) {
                    const uint32_t* bh2 = fbh[nt >> 1] + (nt & 1) * 2;
                    const uint32_t* bl2 = fbl[nt >> 1] + (nt & 1) * 2;
                    mma16816(acc[mt][nt], fah[mt], bh2);
                    mma16816(acc[mt][nt], fah[mt], bl2);
                    mma16816(acc[mt][nt], fal[mt], bh2);
                }
        }
        __syncthreads();
    }

#pragma unroll
    for (int mt = 0; mt < 4; ++mt) {
#pragma unroll
        for (int nt = 0; nt < 4; ++nt) {
            int rr = m0 + wm * 64 + mt * 16 + g;
            int cc = n0 + wn * 32 + nt * 8 + tg * 2;
            float b0 = bias[cc], b1 = bias[cc + 1];
            float v00 = acc[mt][nt][0] + b0, v01 = acc[mt][nt][1] + b1;
            float v10 = acc[mt][nt][2] + b0, v11 = acc[mt][nt][3] + b1;
            if (Cf) {
                *(float2*)&Cf[(size_t)rr * N + cc]       = make_float2(v00, v01);
                *(float2*)&Cf[(size_t)(rr + 8) * N + cc] = make_float2(v10, v11);
            }
            if (Chi) {
                uint32_t h, l;
                split2(v00, v01, h, l);
                *(uint32_t*)&Chi[(size_t)rr * N + cc] = h;
                *(uint32_t*)&Clo[(size_t)rr * N + cc] = l;
                split2(v10, v11, h, l);
                *(uint32_t*)&Chi[(size_t)(rr + 8) * N + cc] = h;
                *(uint32_t*)&Clo[(size_t)(rr + 8) * N + cc] = l;
            }
        }
    }
}

// ---------------------------------------------------------------------------
// HMMA flash attention, pipelined edition.
// CTA per (b, h, 128-query block), 8 warps (256 thr), warp owns 16 rows.
// K/V tiles (64 keys) double-buffered via cp.async. 3-term split precision.
// ---------------------------------------------------------------------------
#define AT_TILE  9216            // 64 rows * 144 B
#define AT_STAGE (4 * AT_TILE)   // Kh,Kl,Vh,Vl  = 36864 B
#define AT_SMEM  (2 * AT_STAGE)  // 73728 B

__global__ __launch_bounds__(256)
void attn_kernel(const bf16* __restrict__ qh, const bf16* __restrict__ ql,
                 bf16* __restrict__ outh, bf16* __restrict__ outl)
{
    extern __shared__ char smc[];
    const int tid = threadIdx.x;
    const int w   = tid >> 5, lane = tid & 31;
    const int g   = lane >> 2, tg = lane & 3;
    const int grp = lane >> 3, ri = lane & 7;
    const int bh  = blockIdx.y;
    const int b   = bh >> 4, h = bh & 15;
    const int qb  = blockIdx.x;
    const float scale = 0.125f;   // 1/sqrt(64)

    const size_t rs = 3 * DIM;
    const size_t tokbase = (size_t)b * SEQ;
    const uint32_t sbase = cvta_smem(smc);

    const uint32_t aLane = (uint32_t)(((grp & 1) * 8 + ri) * 144 + ((grp >> 1) & 1) * 16);
    const uint32_t kLane = (uint32_t)((((grp >> 1) & 1) * 8 + ri) * 144 + (grp & 1) * 16);
    const uint32_t vLane = aLane;

    // ---- stage Q (128 rows: hi at 0, lo at 18432), load fragments ----
#pragma unroll 4
    for (int i = tid; i < 1024; i += 256) {
        int r = i >> 3, c = i & 7;
        size_t go = (tokbase + qb * 128 + r) * rs + h * 64 + c * 8;
        *(uint4*)(smc + r * 144 + c * 16)         = *(const uint4*)(qh + go);
        *(uint4*)(smc + 18432 + r * 144 + c * 16) = *(const uint4*)(ql + go);
    }
    __syncthreads();

    uint32_t fqh[4][4], fql[4][4];
#pragma unroll
    for (int ks = 0; ks < 4; ++ks) {
        uint32_t ro = (uint32_t)(w * 16 * 144 + ks * 32) + aLane;
        ldsm_x4(fqh[ks], sbase + ro);
        ldsm_x4(fql[ks], sbase + 18432 + ro);
    }
    __syncthreads();

    // ---- prefetch helper: tile kb -> stage s ----
    auto prefetch = [&](int kb, int s) {
        uint32_t st = sbase + s * AT_STAGE;
#pragma unroll 2
        for (int i = tid; i < 512; i += 256) {
            int r = i >> 3, c = i & 7;
            size_t gk = (tokbase + kb * 64 + r) * rs + DIM + h * 64 + c * 8;
            uint32_t d = st + r * 144 + c * 16;
            cp_async16(d,               qh + gk);
            cp_async16(d + AT_TILE,     ql + gk);
            cp_async16(d + 2 * AT_TILE, qh + gk + DIM);
            cp_async16(d + 3 * AT_TILE, ql + gk + DIM);
        }
        CP_COMMIT();
    };

    float m0 = -1e30f, m1 = -1e30f, l0 = 0.0f, l1 = 0.0f;
    float o[8][4];
#pragma unroll
    for (int nt = 0; nt < 8; ++nt)
#pragma unroll
        for (int j = 0; j < 4; ++j) o[nt][j] = 0.0f;

    prefetch(0, 0);

    for (int kb = 0; kb < SEQ / 64; ++kb) {
        const int s = kb & 1;
        const bool more = (kb + 1 < SEQ / 64);
        if (more) prefetch(kb + 1, s ^ 1);
        if (more) { CP_WAIT1(); } else { CP_WAIT0(); }
        __syncthreads();

        const uint32_t sKh = sbase + s * AT_STAGE;
        const uint32_t sKl = sKh + AT_TILE;
        const uint32_t sVh = sKh + 2 * AT_TILE;
        const uint32_t sVl = sKh + 3 * AT_TILE;

        // ---- S = Q K^T (3-term) ----
        float sreg[8][4];
#pragma unroll
        for (int nt = 0; nt < 8; ++nt)
#pragma unroll
            for (int j = 0; j < 4; ++j) sreg[nt][j] = 0.0f;

#pragma unroll
        for (int ntp = 0; ntp < 4; ++ntp) {
#pragma unroll
            for (int ks = 0; ks < 4; ++ks) {
                uint32_t ro = (uint32_t)(ntp * 16 * 144 + ks * 32) + kLane;
                uint32_t rh[4], rl[4];
                ldsm_x4(rh, sKh + ro);
                ldsm_x4(rl, sKl + ro);
                mma16816(sreg[2 * ntp],     fqh[ks], rh);
                mma16816(sreg[2 * ntp],     fqh[ks], rl);
                mma16816(sreg[2 * ntp],     fql[ks], rh);
                mma16816(sreg[2 * ntp + 1], fqh[ks], rh + 2);
                mma16816(sreg[2 * ntp + 1], fqh[ks], rl + 2);
                mma16816(sreg[2 * ntp + 1], fql[ks], rh + 2);
            }
        }

        // ---- online softmax ----
        float mx0 = -1e30f, mx1 = -1e30f;
#pragma unroll
        for (int nt = 0; nt < 8; ++nt) {
#pragma unroll
            for (int j = 0; j < 4; ++j) sreg[nt][j] *= scale;
            mx0 = fmaxf(mx0, fmaxf(sreg[nt][0], sreg[nt][1]));
            mx1 = fmaxf(mx1, fmaxf(sreg[nt][2], sreg[nt][3]));
        }
        mx0 = fmaxf(mx0, __shfl_xor_sync(0xffffffffu, mx0, 1));
        mx0 = fmaxf(mx0, __shfl_xor_sync(0xffffffffu, mx0, 2));
        mx1 = fmaxf(mx1, __shfl_xor_sync(0xffffffffu, mx1, 1));
        mx1 = fmaxf(mx1, __shfl_xor_sync(0xffffffffu, mx1, 2));

        float nm0 = fmaxf(m0, mx0), nm1 = fmaxf(m1, mx1);
        float a0 = __expf(m0 - nm0), a1 = __expf(m1 - nm1);
        m0 = nm0; m1 = nm1;

        float sum0 = 0.0f, sum1 = 0.0f;
#pragma unroll
        for (int nt = 0; nt < 8; ++nt) {
            sreg[nt][0] = __expf(sreg[nt][0] - nm0);
            sreg[nt][1] = __expf(sreg[nt][1] - nm0);
            sreg[nt][2] = __expf(sreg[nt][2] - nm1);
            sreg[nt][3] = __expf(sreg[nt][3] - nm1);
            sum0 += sreg[nt][0] + sreg[nt][1];
            sum1 += sreg[nt][2] + sreg[nt][3];
        }
        sum0 += __shfl_xor_sync(0xffffffffu, sum0, 1);
        sum0 += __shfl_xor_sync(0xffffffffu, sum0, 2);
        sum1 += __shfl_xor_sync(0xffffffffu, sum1, 1);
        sum1 += __shfl_xor_sync(0xffffffffu, sum1, 2);
        l0 = l0 * a0 + sum0;
        l1 = l1 * a1 + sum1;

#pragma unroll
        for (int nt = 0; nt < 8; ++nt) {
            o[nt][0] *= a0; o[nt][1] *= a0;
            o[nt][2] *= a1; o[nt][3] *= a1;
        }

        // ---- O += P V (3-term), V B-frags via ldsm.x4.trans ----
#pragma unroll
        for (int ks = 0; ks < 4; ++ks) {
            int t0 = 2 * ks, t1 = 2 * ks + 1;
            uint32_t pah[4], pal[4];
            split2(sreg[t0][0], sreg[t0][1], pah[0], pal[0]);
            split2(sreg[t0][2], sreg[t0][3], pah[1], pal[1]);
            split2(sreg[t1][0], sreg[t1][1], pah[2], pal[2]);
            split2(sreg[t1][2], sreg[t1][3], pah[3], pal[3]);
#pragma unroll
            for (int ntp = 0; ntp < 4; ++ntp) {
                uint32_t ro = (uint32_t)(ks * 16 * 144 + ntp * 32) + vLane;
                uint32_t bvh[4], bvl[4];
                ldsm_x4_t(bvh, sVh + ro);
                ldsm_x4_t(bvl, sVl + ro);
                mma16816(o[2 * ntp],     pah, bvh);
                mma16816(o[2 * ntp],     pah, bvl);
                mma16816(o[2 * ntp],     pal, bvh);
                mma16816(o[2 * ntp + 1], pah, bvh + 2);
                mma16816(o[2 * ntp + 1], pah, bvl + 2);
                mma16816(o[2 * ntp + 1], pal, bvh + 2);
            }
        }
        __syncthreads();
    }

    // ---- epilogue: normalize, split hi/lo, store [token][1024] ----
    float inv0 = 1.0f / l0, inv1 = 1.0f / l1;
    size_t row0 = tokbase + qb * 128 + w * 16 + g;
    size_t row1 = row0 + 8;
#pragma unroll
    for (int nt = 0; nt < 8; ++nt) {
        int cc = h * 64 + nt * 8 + tg * 2;
        uint32_t hh, ll;
        split2(o[nt][0] * inv0, o[nt][1] * inv0, hh, ll);
        *(uint32_t*)&outh[row0 * DIM + cc] = hh;
        *(uint32_t*)&outl[row0 * DIM + cc] = ll;
        split2(o[nt][2] * inv1, o[nt][3] * inv1, hh, ll);
        *(uint32_t*)&outh[row1 * DIM + cc] = hh;
        *(uint32_t*)&outl[row1 * DIM + cc] = ll;
    }
}

// ---------------------------------------------------------------------------
extern "C" void kernel_launch(void* const* d_in, const int* in_sizes, int n_in,
                              void* d_out, int out_size)
{
    const float* x      = (const float*)d_in[0];
    const float* W_qkv  = (const float*)d_in[1];
    const float* b_qkv  = (const float*)d_in[2];
    const float* W_proj = (const float*)d_in[3];
    const float* b_proj = (const float*)d_in[4];
    float* out = (float*)d_out;

    bf16 *qh, *ql, *ah, *al, *bh, *bl;
    cudaGetSymbolAddress((void**)&qh, g_qh);
    cudaGetSymbolAddress((void**)&ql, g_ql);
    cudaGetSymbolAddress((void**)&ah, g_ah);
    cudaGetSymbolAddress((void**)&al, g_al);
    cudaGetSymbolAddress((void**)&bh, g_bh);
    cudaGetSymbolAddress((void**)&bl, g_bl);

    cudaFuncSetAttribute(hmma_gemm, cudaFuncAttributeMaxDynamicSharedMemorySize, GEMM_SMEM);
    cudaFuncSetAttribute(attn_kernel, cudaFuncAttributeMaxDynamicSharedMemorySize, AT_SMEM);

    // 1) split x -> bf16 hi/lo ; W_qkv^T hi/lo
    split_kernel<<<(NTOK * DIM / 4 + 255) / 256, 256>>>(x, ah, al, NTOK * DIM / 4);
    splitT_kernel<<<dim3(3 * DIM / 32, DIM / 32), dim3(32, 8)>>>(W_qkv, bh, bl, DIM, 3 * DIM);

    // 2) QKV projection -> qkv hi/lo bf16 directly
    hmma_gemm<<<dim3(3 * DIM / 128, NTOK / 128), 256, GEMM_SMEM>>>(
        ah, al, bh, bl, b_qkv, nullptr, qh, ql, NTOK, 3 * DIM, DIM);

    // 3) flash attention -> hi/lo bf16 output (into g_ah/g_al)
    attn_kernel<<<dim3(SEQ / 128, BATCH * NH), 256, AT_SMEM>>>(qh, ql, ah, al);

    // 4) W_proj^T hi/lo
    splitT_kernel<<<dim3(DIM / 32, DIM / 32), dim3(32, 8)>>>(W_proj, bh, bl, DIM, DIM);

    // 5) output projection -> fp32 out
    hmma_gemm<<<dim3(DIM / 128, NTOK / 128), 256, GEMM_SMEM>>>(
        ah, al, bh, bl, b_proj, out, nullptr, nullptr, NTOK, DIM, DIM);
}